// round 13
// baseline (speedup 1.0000x reference)
#include <cuda_runtime.h>
#include <cuda_fp16.h>
#include <cstdint>

#define BB 8
#define NN 2048
#define IND 256
#define OUTD 128
#define ROWS (BB * NN)   // 16384
#define NEG_SLOPE 0.2f

// Scratch (device globals — no allocation allowed)
__device__ __half g_WhT[(size_t)ROWS * OUTD];  // 4 MB, per-batch [o][j] fp16
__device__ float g_E1[ROWS];          // exp(f1)
__device__ float g_G1[ROWS];          // exp(0.2*f1)
__device__ float g_E2[ROWS];          // exp(f2)
__device__ float g_G2[ROWS];          // exp(0.2*f2)

__device__ __forceinline__ void cp_async16(void* dst_smem, const void* src) {
    uint32_t d = (uint32_t)__cvta_generic_to_shared(dst_smem);
    asm volatile("cp.async.cg.shared.global [%0], [%1], 16;\n"
                 :: "r"(d), "l"(src));
}
#define CP_COMMIT() asm volatile("cp.async.commit_group;\n" ::: "memory")
#define CP_WAIT(N)  asm volatile("cp.async.wait_group %0;\n" :: "n"(N) : "memory")

// ---------------------------------------------------------------------------
// Kernel 1: Wh = h @ W (unchanged, proven). f1/f2 full precision -> exp
// factors; Wh stored fp16 transposed per batch: g_WhT[b][o][j].
// ---------------------------------------------------------------------------
__global__ __launch_bounds__(256) void k1_gemm_wh(
    const float* __restrict__ h, const float* __restrict__ W,
    const float* __restrict__ a)
{
    __shared__ float hs[64][32];
    __shared__ float Ws[32][128];

    const int t  = threadIdx.x;
    const int ty = t >> 5;
    const int tx = t & 31;
    const int row0 = blockIdx.x * 64;

    float acc[8][4];
    #pragma unroll
    for (int i = 0; i < 8; i++)
        #pragma unroll
        for (int j = 0; j < 4; j++) acc[i][j] = 0.f;

    float a1v[4], a2v[4];
    #pragma unroll
    for (int cc = 0; cc < 4; cc++) {
        a1v[cc] = a[tx * 4 + cc];
        a2v[cc] = a[OUTD + tx * 4 + cc];
    }

    const int lr = t >> 3;
    const int lc = (t & 7) * 4;

    for (int k0 = 0; k0 < IND; k0 += 32) {
        *(float4*)&hs[lr][lc] =
            *(const float4*)&h[(size_t)(row0 + lr) * IND + k0 + lc];
        *(float4*)&hs[lr + 32][lc] =
            *(const float4*)&h[(size_t)(row0 + lr + 32) * IND + k0 + lc];
        #pragma unroll
        for (int p = 0; p < 4; p++) {
            int idx = t * 4 + p * 1024;
            int wr = idx >> 7, wc = idx & 127;
            *(float4*)&Ws[wr][wc] = *(const float4*)&W[(size_t)(k0 + wr) * OUTD + wc];
        }
        __syncthreads();

        #pragma unroll 8
        for (int kk = 0; kk < 32; kk++) {
            float4 wq = *(const float4*)&Ws[kk][tx * 4];
            #pragma unroll
            for (int rr = 0; rr < 8; rr++) {
                float hv = hs[ty * 8 + rr][kk];
                acc[rr][0] += hv * wq.x;
                acc[rr][1] += hv * wq.y;
                acc[rr][2] += hv * wq.z;
                acc[rr][3] += hv * wq.w;
            }
        }
        __syncthreads();
    }

    {
        const int bb = row0 >> 11;             // batch
        const int jloc = (row0 & (NN - 1)) + ty * 8;
        __half* WhTb = g_WhT + (size_t)bb * OUTD * NN;
        #pragma unroll
        for (int cc = 0; cc < 4; cc++) {
            const int c = tx * 4 + cc;
            __half hv[8];
            #pragma unroll
            for (int rr = 0; rr < 8; rr++) hv[rr] = __float2half_rn(acc[rr][cc]);
            *(uint4*)&WhTb[(size_t)c * NN + jloc] = *(const uint4*)hv;
        }
    }

    #pragma unroll
    for (int rr = 0; rr < 8; rr++) {
        const int r = row0 + ty * 8 + rr;
        float s1 = acc[rr][0] * a1v[0] + acc[rr][1] * a1v[1] +
                   acc[rr][2] * a1v[2] + acc[rr][3] * a1v[3];
        float s2 = acc[rr][0] * a2v[0] + acc[rr][1] * a2v[1] +
                   acc[rr][2] * a2v[2] + acc[rr][3] * a2v[3];
        #pragma unroll
        for (int off = 16; off; off >>= 1) {
            s1 += __shfl_xor_sync(0xFFFFFFFFu, s1, off);
            s2 += __shfl_xor_sync(0xFFFFFFFFu, s2, off);
        }
        if (tx == 0) {
            g_E1[r] = expf(s1);
            g_G1[r] = expf(NEG_SLOPE * s1);
            g_E2[r] = expf(s2);
            g_G2[r] = expf(NEG_SLOPE * s2);
        }
    }
}

// ---------------------------------------------------------------------------
// Kernel 2: fp16 mma m16n8k16, ldmatrix fragments, ONE barrier per tile.
// adj/E2/G2 read by direct LDG in the weight phase (L2-resident; this is the
// round-9-proven placement — no cross-thread smem visibility needed).
// Wh tile cp.async double-buffered; wts double-buffered (WAR distance 2 tiles
// with a barrier between -> single __syncthreads per tile is sufficient:
//   weights(t)->wts[p] happens after sync(t-1); last reads of wts[p] were
//   MMA(t-2), issued before sync(t-1) in every warp's program order).
// per tile t (p = t&1):
//   weights(t): LDG adj/ej/gj, compute, STS -> wts[p]
//   CP_WAIT(0)        (own Wh(t) chunks landed)
//   __syncthreads()   (all Wh(t)+wts(t) visible; MMA(t-1) done everywhere)
//   prefetch Wh(t+1)  (overlaps MMA(t) and weights(t+1))
//   MMA(t): ldmatrix.x4 A/B + 32 mma
// ---------------------------------------------------------------------------
#define BSTRIDE 36                    // words per fragment row (72 halves)
#define WHT_WORDS (128 * BSTRIDE)     // 4608 per buffer
#define WTS_WORDS (64 * BSTRIDE)      // 2304 per buffer
#define SM_WHT 0                       // [2][WHT_WORDS]
#define SM_WTS (2 * WHT_WORDS)         // 9216, [2][WTS_WORDS]
#define SM_ZS  (SM_WTS + 2 * WTS_WORDS)  // 13824
#define SM_TOT (SM_ZS + 64)
#define SM_BYTES (SM_TOT * 4)          // 55552 B

__device__ __forceinline__ void mma_f16(float* d, const uint32_t* a,
                                        uint32_t b0, uint32_t b1) {
    asm volatile(
        "mma.sync.aligned.m16n8k16.row.col.f32.f16.f16.f32 "
        "{%0,%1,%2,%3}, {%4,%5,%6,%7}, {%8,%9}, {%0,%1,%2,%3};\n"
        : "+f"(d[0]), "+f"(d[1]), "+f"(d[2]), "+f"(d[3])
        : "r"(a[0]), "r"(a[1]), "r"(a[2]), "r"(a[3]), "r"(b0), "r"(b1));
}

__device__ __forceinline__ void ldsm4(uint32_t addr, uint32_t* r) {
    asm volatile("ldmatrix.sync.aligned.m8n8.x4.shared.b16 {%0,%1,%2,%3}, [%4];"
                 : "=r"(r[0]), "=r"(r[1]), "=r"(r[2]), "=r"(r[3]) : "r"(addr));
}

__device__ __forceinline__ void prefetch_wh(uint32_t* WhTs,
                                            const __half* WhTb,
                                            int buf, int j0, int t) {
    uint32_t* whDst = WhTs + buf * WHT_WORDS;
    #pragma unroll
    for (int p = 0; p < 4; p++) {
        int c = t + p * 256;            // chunk 0..1023
        int o = c >> 3, ch = c & 7;
        cp_async16(&whDst[o * BSTRIDE + ch * 4],
                   &WhTb[(size_t)o * NN + j0 + ch * 8]);
    }
    CP_COMMIT();
}

__global__ __launch_bounds__(256, 2) void k2_attn(
    const float* __restrict__ adj, float* __restrict__ out)
{
    extern __shared__ uint32_t smw[];
    uint32_t* WhTs = smw + SM_WHT;
    uint32_t* wts  = smw + SM_WTS;
    float* Zs = (float*)(smw + SM_ZS);

    const int t    = threadIdx.x;
    const int wid  = t >> 5;
    const int lane = t & 31;
    const int gid  = lane >> 2;
    const int tig  = lane & 3;
    const int b    = blockIdx.y;
    const int i0   = blockIdx.x * 64;

    const int m_warp = (wid & 1) * 32;      // 2 m-warps x 4 n-warps
    const int n_warp = (wid >> 1) * 32;

    const int wr  = t >> 2;          // weight row 0..63
    const int wc0 = (t & 3) * 16;    // weight col base

    if (t < 64) Zs[t] = 0.f;

    const float Efi = g_E1[(size_t)b * NN + i0 + wr];
    const float Gfi = g_G1[(size_t)b * NN + i0 + wr];
    const __half* WhTb = g_WhT + (size_t)b * OUTD * NN;
    const float* E2b = g_E2 + (size_t)b * NN;
    const float* G2b = g_G2 + (size_t)b * NN;
    const float* adjrow = adj + (size_t)(i0 + wr) * NN + wc0;

    // ldmatrix lane base addresses (shared-space byte offsets)
    const uint32_t smem0 = (uint32_t)__cvta_generic_to_shared(smw);
    const uint32_t aBase = smem0 + SM_WTS * 4 +
        (uint32_t)(((m_warp + (lane & 15)) * BSTRIDE + (lane >> 4) * 4) * 4);
    const uint32_t bBase = smem0 + SM_WHT * 4 +
        (uint32_t)(((n_warp + ((lane >> 4) & 1) * 8 + (lane & 7)) * BSTRIDE +
                    ((lane >> 3) & 1) * 4) * 4);

    // prologue: Wh tile 0
    prefetch_wh(WhTs, WhTb, 0, 0, t);

    float acc[2][4][4];
    #pragma unroll
    for (int u = 0; u < 2; u++)
        #pragma unroll
        for (int v = 0; v < 4; v++)
            #pragma unroll
            for (int j = 0; j < 4; j++) acc[u][v][j] = 0.f;

    float Zpart = 0.f;

    for (int tt = 0; tt < NN / 64; tt++) {
        const int idx = tt & 1;
        const int j0 = tt * 64;

        // ---- weight tile: direct LDG (L2-resident), fp16-rounded
        {
            uint32_t wb[8];
            #pragma unroll
            for (int q = 0; q < 4; q++) {
                float4 av = *(const float4*)&adjrow[j0 + q * 4];
                float4 ej = *(const float4*)&E2b[j0 + wc0 + q * 4];
                float4 gj = *(const float4*)&G2b[j0 + wc0 + q * 4];
                float w0 = fmaxf(Efi * ej.x, Gfi * gj.x) * av.x;
                float w1 = fmaxf(Efi * ej.y, Gfi * gj.y) * av.y;
                float w2 = fmaxf(Efi * ej.z, Gfi * gj.z) * av.z;
                float w3 = fmaxf(Efi * ej.w, Gfi * gj.w) * av.w;
                __half2 p0 = __floats2half2_rn(w0, w1);
                __half2 p1 = __floats2half2_rn(w2, w3);
                float2 r0 = __half22float2(p0);
                float2 r1 = __half22float2(p1);
                Zpart += (r0.x + r0.y) + (r1.x + r1.y);
                wb[q * 2]     = *(const uint32_t*)&p0;
                wb[q * 2 + 1] = *(const uint32_t*)&p1;
            }
            uint32_t* dst = &wts[idx * WTS_WORDS + wr * BSTRIDE + (t & 3) * 8];
            *(uint4*)dst       = make_uint4(wb[0], wb[1], wb[2], wb[3]);
            *(uint4*)(dst + 4) = make_uint4(wb[4], wb[5], wb[6], wb[7]);
        }

        CP_WAIT(0);               // own Wh(tt) chunks landed
        __syncthreads();          // the ONE barrier per tile

        if (tt + 1 < NN / 64)
            prefetch_wh(WhTs, WhTb, idx ^ 1, j0 + 64, t);

        // ---- MMA via ldmatrix: acc += wts(64x64) @ Wh(64x128)
        const uint32_t aT = aBase + (uint32_t)(idx * WTS_WORDS * 4);
        const uint32_t bT = bBase + (uint32_t)(idx * WHT_WORDS * 4);
        #pragma unroll
        for (int kw = 0; kw < 4; kw++) {
            uint32_t af[2][4], bf[2][4];
            ldsm4(aT + kw * 32,        af[0]);
            ldsm4(aT + 2304 + kw * 32, af[1]);   // +16 rows * 144 B
            ldsm4(bT + kw * 32,        bf[0]);   // n 0..15
            ldsm4(bT + 2304 + kw * 32, bf[1]);   // n 16..31
            #pragma unroll
            for (int u = 0; u < 2; u++) {
                mma_f16(acc[u][0], af[u], bf[0][0], bf[0][1]);
                mma_f16(acc[u][1], af[u], bf[0][2], bf[0][3]);
                mma_f16(acc[u][2], af[u], bf[1][0], bf[1][1]);
                mma_f16(acc[u][3], af[u], bf[1][2], bf[1][3]);
            }
        }
    }

    atomicAdd(&Zs[wr], Zpart);
    __syncthreads();

    // ---- epilogue: divide by Z, store
    #pragma unroll
    for (int u = 0; u < 2; u++) {
        const int row0e = m_warp + u * 16 + gid;
        const int row1e = row0e + 8;
        const float inv0 = 1.f / Zs[row0e];
        const float inv1 = 1.f / Zs[row1e];
        float* out0 = out + ((size_t)b * NN + i0 + row0e) * OUTD;
        float* out1 = out + ((size_t)b * NN + i0 + row1e) * OUTD;
        #pragma unroll
        for (int v = 0; v < 4; v++) {
            int col = n_warp + v * 8 + tig * 2;
            *(float2*)&out0[col] = make_float2(acc[u][v][0] * inv0,
                                               acc[u][v][1] * inv0);
            *(float2*)&out1[col] = make_float2(acc[u][v][2] * inv1,
                                               acc[u][v][3] * inv1);
        }
    }
}

// ---------------------------------------------------------------------------
extern "C" void kernel_launch(void* const* d_in, const int* in_sizes, int n_in,
                              void* d_out, int out_size)
{
    const float* h   = (const float*)d_in[0];   // (8, 2048, 256)
    const float* adj = (const float*)d_in[1];   // (2048, 2048)
    const float* W   = (const float*)d_in[2];   // (256, 128)
    const float* a   = (const float*)d_in[3];   // (256,)
    float* out = (float*)d_out;                 // (8, 2048, 128)

    k1_gemm_wh<<<ROWS / 64, 256>>>(h, W, a);

    cudaFuncSetAttribute(k2_attn, cudaFuncAttributeMaxDynamicSharedMemorySize,
                         SM_BYTES);
    k2_attn<<<dim3(NN / 64, BB), 256, SM_BYTES>>>(adj, out);
}

// round 14
// speedup vs baseline: 1.1641x; 1.1641x over previous
#include <cuda_runtime.h>
#include <cuda_fp16.h>
#include <cstdint>

#define BB 8
#define NN 2048
#define IND 256
#define OUTD 128
#define ROWS (BB * NN)   // 16384
#define NEG_SLOPE 0.2f

// Scratch (device globals — no allocation allowed)
__device__ __half g_WhT[(size_t)ROWS * OUTD];  // 4 MB, per-batch [o][j] fp16
__device__ float g_E1[ROWS];          // exp(f1)
__device__ float g_G1[ROWS];          // exp(0.2*f1)
__device__ float g_E2[ROWS];          // exp(f2)
__device__ float g_G2[ROWS];          // exp(0.2*f2)
__device__ uint32_t g_adjm[(NN / 32) * NN];   // 512 KB, [jw][i] bitmask

__device__ __forceinline__ void cp_async16(void* dst_smem, const void* src) {
    uint32_t d = (uint32_t)__cvta_generic_to_shared(dst_smem);
    asm volatile("cp.async.cg.shared.global [%0], [%1], 16;\n"
                 :: "r"(d), "l"(src));
}
#define CP_COMMIT() asm volatile("cp.async.commit_group;\n" ::: "memory")
#define CP_WAIT(N)  asm volatile("cp.async.wait_group %0;\n" :: "n"(N) : "memory")

// ---------------------------------------------------------------------------
// Kernel 0: pack adj>0 into transposed bitmask  adjmT[j/32][i].
// Warp-ballot: lane l tests adj[i][jw*32+l]; reads perfectly coalesced.
// ---------------------------------------------------------------------------
__global__ __launch_bounds__(256) void k0_pack_adj(const float* __restrict__ adj)
{
    const int i    = blockIdx.x;          // row 0..2047
    const int warp = threadIdx.x >> 5;    // 0..7
    const int lane = threadIdx.x & 31;
    #pragma unroll
    for (int k = 0; k < 8; k++) {
        const int jw = warp + k * 8;      // 0..63
        float v = adj[(size_t)i * NN + jw * 32 + lane];
        uint32_t m = __ballot_sync(0xFFFFFFFFu, v > 0.f);
        if (lane == 0) g_adjm[jw * NN + i] = m;
    }
}

// ---------------------------------------------------------------------------
// Kernel 1: Wh = h @ W (unchanged, proven). f1/f2 full precision -> exp
// factors; Wh stored fp16 transposed per batch: g_WhT[b][o][j].
// ---------------------------------------------------------------------------
__global__ __launch_bounds__(256) void k1_gemm_wh(
    const float* __restrict__ h, const float* __restrict__ W,
    const float* __restrict__ a)
{
    __shared__ float hs[64][32];
    __shared__ float Ws[32][128];

    const int t  = threadIdx.x;
    const int ty = t >> 5;
    const int tx = t & 31;
    const int row0 = blockIdx.x * 64;

    float acc[8][4];
    #pragma unroll
    for (int i = 0; i < 8; i++)
        #pragma unroll
        for (int j = 0; j < 4; j++) acc[i][j] = 0.f;

    float a1v[4], a2v[4];
    #pragma unroll
    for (int cc = 0; cc < 4; cc++) {
        a1v[cc] = a[tx * 4 + cc];
        a2v[cc] = a[OUTD + tx * 4 + cc];
    }

    const int lr = t >> 3;
    const int lc = (t & 7) * 4;

    for (int k0 = 0; k0 < IND; k0 += 32) {
        *(float4*)&hs[lr][lc] =
            *(const float4*)&h[(size_t)(row0 + lr) * IND + k0 + lc];
        *(float4*)&hs[lr + 32][lc] =
            *(const float4*)&h[(size_t)(row0 + lr + 32) * IND + k0 + lc];
        #pragma unroll
        for (int p = 0; p < 4; p++) {
            int idx = t * 4 + p * 1024;
            int wr = idx >> 7, wc = idx & 127;
            *(float4*)&Ws[wr][wc] = *(const float4*)&W[(size_t)(k0 + wr) * OUTD + wc];
        }
        __syncthreads();

        #pragma unroll 8
        for (int kk = 0; kk < 32; kk++) {
            float4 wq = *(const float4*)&Ws[kk][tx * 4];
            #pragma unroll
            for (int rr = 0; rr < 8; rr++) {
                float hv = hs[ty * 8 + rr][kk];
                acc[rr][0] += hv * wq.x;
                acc[rr][1] += hv * wq.y;
                acc[rr][2] += hv * wq.z;
                acc[rr][3] += hv * wq.w;
            }
        }
        __syncthreads();
    }

    {
        const int bb = row0 >> 11;             // batch
        const int jloc = (row0 & (NN - 1)) + ty * 8;
        __half* WhTb = g_WhT + (size_t)bb * OUTD * NN;
        #pragma unroll
        for (int cc = 0; cc < 4; cc++) {
            const int c = tx * 4 + cc;
            __half hv[8];
            #pragma unroll
            for (int rr = 0; rr < 8; rr++) hv[rr] = __float2half_rn(acc[rr][cc]);
            *(uint4*)&WhTb[(size_t)c * NN + jloc] = *(const uint4*)hv;
        }
    }

    #pragma unroll
    for (int rr = 0; rr < 8; rr++) {
        const int r = row0 + ty * 8 + rr;
        float s1 = acc[rr][0] * a1v[0] + acc[rr][1] * a1v[1] +
                   acc[rr][2] * a1v[2] + acc[rr][3] * a1v[3];
        float s2 = acc[rr][0] * a2v[0] + acc[rr][1] * a2v[1] +
                   acc[rr][2] * a2v[2] + acc[rr][3] * a2v[3];
        #pragma unroll
        for (int off = 16; off; off >>= 1) {
            s1 += __shfl_xor_sync(0xFFFFFFFFu, s1, off);
            s2 += __shfl_xor_sync(0xFFFFFFFFu, s2, off);
        }
        if (tx == 0) {
            g_E1[r] = expf(s1);
            g_G1[r] = expf(NEG_SLOPE * s1);
            g_E2[r] = expf(s2);
            g_G2[r] = expf(NEG_SLOPE * s2);
        }
    }
}

// ---------------------------------------------------------------------------
// Kernel 2: fp16 mma m16n8k16, ldmatrix fragments, ONE barrier per tile.
// adj mask now ONE LDG.32 per thread per tile (bitmask), ej/gj direct LDG
// (L2-resident). Wh tile cp.async double-buffered; wts double-buffered.
// Pipeline and sync structure identical to round 13 (proven).
// ---------------------------------------------------------------------------
#define BSTRIDE 36                    // words per fragment row (72 halves)
#define WHT_WORDS (128 * BSTRIDE)     // 4608 per buffer
#define WTS_WORDS (64 * BSTRIDE)      // 2304 per buffer
#define SM_WHT 0                       // [2][WHT_WORDS]
#define SM_WTS (2 * WHT_WORDS)         // 9216, [2][WTS_WORDS]
#define SM_ZS  (SM_WTS + 2 * WTS_WORDS)  // 13824
#define SM_TOT (SM_ZS + 64)
#define SM_BYTES (SM_TOT * 4)          // 55552 B

__device__ __forceinline__ void mma_f16(float* d, const uint32_t* a,
                                        uint32_t b0, uint32_t b1) {
    asm volatile(
        "mma.sync.aligned.m16n8k16.row.col.f32.f16.f16.f32 "
        "{%0,%1,%2,%3}, {%4,%5,%6,%7}, {%8,%9}, {%0,%1,%2,%3};\n"
        : "+f"(d[0]), "+f"(d[1]), "+f"(d[2]), "+f"(d[3])
        : "r"(a[0]), "r"(a[1]), "r"(a[2]), "r"(a[3]), "r"(b0), "r"(b1));
}

__device__ __forceinline__ void ldsm4(uint32_t addr, uint32_t* r) {
    asm volatile("ldmatrix.sync.aligned.m8n8.x4.shared.b16 {%0,%1,%2,%3}, [%4];"
                 : "=r"(r[0]), "=r"(r[1]), "=r"(r[2]), "=r"(r[3]) : "r"(addr));
}

__device__ __forceinline__ void prefetch_wh(uint32_t* WhTs,
                                            const __half* WhTb,
                                            int buf, int j0, int t) {
    uint32_t* whDst = WhTs + buf * WHT_WORDS;
    #pragma unroll
    for (int p = 0; p < 4; p++) {
        int c = t + p * 256;            // chunk 0..1023
        int o = c >> 3, ch = c & 7;
        cp_async16(&whDst[o * BSTRIDE + ch * 4],
                   &WhTb[(size_t)o * NN + j0 + ch * 8]);
    }
    CP_COMMIT();
}

__global__ __launch_bounds__(256, 2) void k2_attn(
    const float* __restrict__ adj, float* __restrict__ out)
{
    extern __shared__ uint32_t smw[];
    uint32_t* WhTs = smw + SM_WHT;
    uint32_t* wts  = smw + SM_WTS;
    float* Zs = (float*)(smw + SM_ZS);

    const int t    = threadIdx.x;
    const int wid  = t >> 5;
    const int lane = t & 31;
    const int gid  = lane >> 2;
    const int tig  = lane & 3;
    const int b    = blockIdx.y;
    const int i0   = blockIdx.x * 64;

    const int m_warp = (wid & 1) * 32;      // 2 m-warps x 4 n-warps
    const int n_warp = (wid >> 1) * 32;

    const int wr  = t >> 2;          // weight row 0..63
    const int wc0 = (t & 3) * 16;    // weight col base

    if (t < 64) Zs[t] = 0.f;

    const float Efi = g_E1[(size_t)b * NN + i0 + wr];
    const float Gfi = g_G1[(size_t)b * NN + i0 + wr];
    const __half* WhTb = g_WhT + (size_t)b * OUTD * NN;
    const float* E2b = g_E2 + (size_t)b * NN;
    const float* G2b = g_G2 + (size_t)b * NN;
    // mask base: word jw = j0/32 + (t&3)/2, row i0+wr; per tile advance 2*NN
    const uint32_t* mbase = g_adjm + ((t & 3) >> 1) * NN + i0 + wr;
    const int msh = (t & 1) * 16;    // which 16-bit half of the word

    // ldmatrix lane base addresses (shared-space byte offsets)
    const uint32_t smem0 = (uint32_t)__cvta_generic_to_shared(smw);
    const uint32_t aBase = smem0 + SM_WTS * 4 +
        (uint32_t)(((m_warp + (lane & 15)) * BSTRIDE + (lane >> 4) * 4) * 4);
    const uint32_t bBase = smem0 + SM_WHT * 4 +
        (uint32_t)(((n_warp + ((lane >> 4) & 1) * 8 + (lane & 7)) * BSTRIDE +
                    ((lane >> 3) & 1) * 4) * 4);

    // prologue: Wh tile 0
    prefetch_wh(WhTs, WhTb, 0, 0, t);

    float acc[2][4][4];
    #pragma unroll
    for (int u = 0; u < 2; u++)
        #pragma unroll
        for (int v = 0; v < 4; v++)
            #pragma unroll
            for (int j = 0; j < 4; j++) acc[u][v][j] = 0.f;

    float Zpart = 0.f;

    for (int tt = 0; tt < NN / 64; tt++) {
        const int idx = tt & 1;
        const int j0 = tt * 64;

        // ---- weight tile: 1 mask word + ej/gj LDG, fp16-rounded
        {
            const uint32_t mbits = mbase[(size_t)tt * 2 * NN] >> msh;
            uint32_t wb[8];
            #pragma unroll
            for (int q = 0; q < 4; q++) {
                float4 ej = *(const float4*)&E2b[j0 + wc0 + q * 4];
                float4 gj = *(const float4*)&G2b[j0 + wc0 + q * 4];
                float w0 = fmaxf(Efi * ej.x, Gfi * gj.x);
                float w1 = fmaxf(Efi * ej.y, Gfi * gj.y);
                float w2 = fmaxf(Efi * ej.z, Gfi * gj.z);
                float w3 = fmaxf(Efi * ej.w, Gfi * gj.w);
                w0 = (mbits & (1u << (q * 4 + 0))) ? w0 : 0.f;
                w1 = (mbits & (1u << (q * 4 + 1))) ? w1 : 0.f;
                w2 = (mbits & (1u << (q * 4 + 2))) ? w2 : 0.f;
                w3 = (mbits & (1u << (q * 4 + 3))) ? w3 : 0.f;
                __half2 p0 = __floats2half2_rn(w0, w1);
                __half2 p1 = __floats2half2_rn(w2, w3);
                float2 r0 = __half22float2(p0);
                float2 r1 = __half22float2(p1);
                Zpart += (r0.x + r0.y) + (r1.x + r1.y);
                wb[q * 2]     = *(const uint32_t*)&p0;
                wb[q * 2 + 1] = *(const uint32_t*)&p1;
            }
            uint32_t* dst = &wts[idx * WTS_WORDS + wr * BSTRIDE + (t & 3) * 8];
            *(uint4*)dst       = make_uint4(wb[0], wb[1], wb[2], wb[3]);
            *(uint4*)(dst + 4) = make_uint4(wb[4], wb[5], wb[6], wb[7]);
        }

        CP_WAIT(0);               // own Wh(tt) chunks landed
        __syncthreads();          // the ONE barrier per tile

        if (tt + 1 < NN / 64)
            prefetch_wh(WhTs, WhTb, idx ^ 1, j0 + 64, t);

        // ---- MMA via ldmatrix: acc += wts(64x64) @ Wh(64x128)
        const uint32_t aT = aBase + (uint32_t)(idx * WTS_WORDS * 4);
        const uint32_t bT = bBase + (uint32_t)(idx * WHT_WORDS * 4);
        #pragma unroll
        for (int kw = 0; kw < 4; kw++) {
            uint32_t af[2][4], bf[2][4];
            ldsm4(aT + kw * 32,        af[0]);
            ldsm4(aT + 2304 + kw * 32, af[1]);   // +16 rows * 144 B
            ldsm4(bT + kw * 32,        bf[0]);   // n 0..15
            ldsm4(bT + 2304 + kw * 32, bf[1]);   // n 16..31
            #pragma unroll
            for (int u = 0; u < 2; u++) {
                mma_f16(acc[u][0], af[u], bf[0][0], bf[0][1]);
                mma_f16(acc[u][1], af[u], bf[0][2], bf[0][3]);
                mma_f16(acc[u][2], af[u], bf[1][0], bf[1][1]);
                mma_f16(acc[u][3], af[u], bf[1][2], bf[1][3]);
            }
        }
    }

    atomicAdd(&Zs[wr], Zpart);
    __syncthreads();

    // ---- epilogue: divide by Z, store
    #pragma unroll
    for (int u = 0; u < 2; u++) {
        const int row0e = m_warp + u * 16 + gid;
        const int row1e = row0e + 8;
        const float inv0 = 1.f / Zs[row0e];
        const float inv1 = 1.f / Zs[row1e];
        float* out0 = out + ((size_t)b * NN + i0 + row0e) * OUTD;
        float* out1 = out + ((size_t)b * NN + i0 + row1e) * OUTD;
        #pragma unroll
        for (int v = 0; v < 4; v++) {
            int col = n_warp + v * 8 + tig * 2;
            *(float2*)&out0[col] = make_float2(acc[u][v][0] * inv0,
                                               acc[u][v][1] * inv0);
            *(float2*)&out1[col] = make_float2(acc[u][v][2] * inv1,
                                               acc[u][v][3] * inv1);
        }
    }
}

// ---------------------------------------------------------------------------
extern "C" void kernel_launch(void* const* d_in, const int* in_sizes, int n_in,
                              void* d_out, int out_size)
{
    const float* h   = (const float*)d_in[0];   // (8, 2048, 256)
    const float* adj = (const float*)d_in[1];   // (2048, 2048)
    const float* W   = (const float*)d_in[2];   // (256, 128)
    const float* a   = (const float*)d_in[3];   // (256,)
    float* out = (float*)d_out;                 // (8, 2048, 128)

    k0_pack_adj<<<NN, 256>>>(adj);
    k1_gemm_wh<<<ROWS / 64, 256>>>(h, W, a);

    cudaFuncSetAttribute(k2_attn, cudaFuncAttributeMaxDynamicSharedMemorySize,
                         SM_BYTES);
    k2_attn<<<dim3(NN / 64, BB), 256, SM_BYTES>>>(adj, out);
}